// round 12
// baseline (speedup 1.0000x reference)
#include <cuda_runtime.h>

// OpticalFlow dense_image_warp: image [8,512,512,16] f32, flow [8,512,512,2] f32
// out[b,y,x,c] = bilinear sample at (y - flow[...,0], x - flow[...,1]), edge clamp.
//
// R2: 4 threads/pixel channel-parallel (59.4us) — right memory pattern.
// R7/R9: +2 x-adjacent px/thread, regs 32, 32-bit idx, saturatef (57.1us).
// R8/R10: block-size gradient: 512 -> 76us, 256 -> 57.1us, 128 -> 53.7us.
//         Smaller per-block LDG bursts smooth the L1tex queue.
// R11: next step of the same gradient: 64-thread blocks,
//      __launch_bounds__(64,32) — still 2048 thr/SM (32-CTA cap).

#define B 8
#define H 512
#define W 512
#define HW (H * W)
#define NPIX (B * HW)
#define NTHREADS_TOTAL (NPIX * 2)   // 4 threads per 2-pixel pair

__device__ __forceinline__ float4 blend4(float4 tl, float4 tr, float4 bl, float4 br,
                                         float ax, float ay)
{
    float4 r;
    float tp, bt;
    tp = tl.x + ax * (tr.x - tl.x); bt = bl.x + ax * (br.x - bl.x); r.x = tp + ay * (bt - tp);
    tp = tl.y + ax * (tr.y - tl.y); bt = bl.y + ax * (br.y - bl.y); r.y = tp + ay * (bt - tp);
    tp = tl.z + ax * (tr.z - tl.z); bt = bl.z + ax * (br.z - bl.z); r.z = tp + ay * (bt - tp);
    tp = tl.w + ax * (tr.w - tl.w); bt = bl.w + ax * (br.w - bl.w); r.w = tp + ay * (bt - tp);
    return r;
}

__global__ __launch_bounds__(64, 32) void warp_kernel(
    const float* __restrict__ image,
    const float* __restrict__ flow,
    float* __restrict__ out)
{
    unsigned t = blockIdx.x * blockDim.x + threadIdx.x;

    unsigned g  = t & 3u;        // channel group 0..3
    unsigned pp = t >> 2;        // pixel-pair index
    unsigned pix0 = pp << 1;     // even pixel; pix1 = pix0+1 (same row: W even)

    unsigned b = pix0 >> 18;
    unsigned p = pix0 & (HW - 1);
    unsigned y = p >> 9;
    unsigned x = p & 511u;       // even; x+1 < 512 always

    // both pixels' flow in one float4; streamed (no reuse)
    float4 f = __ldcs(((const float4*)flow) + pp);

    // pixel 0
    float qy0 = (float)y - f.x;
    float qx0 = (float)x - f.y;
    float fy0 = fminf(fmaxf(floorf(qy0), 0.0f), (float)(H - 2));
    float fx0 = fminf(fmaxf(floorf(qx0), 0.0f), (float)(W - 2));
    float ay0 = __saturatef(qy0 - fy0);   // fy0 pre-clamped -> identical to clip(0,1)
    float ax0 = __saturatef(qx0 - fx0);
    int iy0 = (int)fy0, ix0 = (int)fx0;

    // pixel 1
    float qy1 = (float)y - f.z;
    float qx1 = (float)(x + 1) - f.w;
    float fy1 = fminf(fmaxf(floorf(qy1), 0.0f), (float)(H - 2));
    float fx1 = fminf(fmaxf(floorf(qx1), 0.0f), (float)(W - 2));
    float ay1 = __saturatef(qy1 - fy1);
    float ax1 = __saturatef(qx1 - fx1);
    int iy1 = (int)fy1, ix1 = (int)fx1;

    // 32-bit float4 indexing throughout (image = 33.5M float4 < 2^31)
    const float4* base = (const float4*)image + b * (unsigned)(HW * 4);
    unsigned a_tl = (unsigned)(iy0 * W + ix0) * 4u + g;
    unsigned a_bl = a_tl + W * 4u;
    unsigned b_tl = (unsigned)(iy1 * W + ix1) * 4u + g;
    unsigned b_bl = b_tl + W * 4u;

    // front-batch all 8 gathers (plus flow already in flight: 9 loads)
    float4 tl0 = __ldg(base + a_tl);
    float4 tr0 = __ldg(base + a_tl + 4);
    float4 bl0 = __ldg(base + a_bl);
    float4 br0 = __ldg(base + a_bl + 4);
    float4 tl1 = __ldg(base + b_tl);
    float4 tr1 = __ldg(base + b_tl + 4);
    float4 bl1 = __ldg(base + b_bl);
    float4 br1 = __ldg(base + b_bl + 4);

    float4 r0 = blend4(tl0, tr0, bl0, br0, ax0, ay0);
    float4 r1 = blend4(tl1, tr1, bl1, br1, ax1, ay1);

    unsigned o0 = pix0 * 4u + g;          // out float4 index, 32-bit
    __stcs(((float4*)out) + o0, r0);
    __stcs(((float4*)out) + o0 + 4u, r1);
}

extern "C" void kernel_launch(void* const* d_in, const int* in_sizes, int n_in,
                              void* d_out, int out_size)
{
    const float* image = (const float*)d_in[0];
    const float* flow  = (const float*)d_in[1];
    float* out = (float*)d_out;

    int threads = 64;
    int blocks = NTHREADS_TOTAL / threads;   // 65536
    warp_kernel<<<blocks, threads>>>(image, flow, out);
}

// round 13
// speedup vs baseline: 1.0018x; 1.0018x over previous
#include <cuda_runtime.h>

// OpticalFlow dense_image_warp: image [8,512,512,16] f32, flow [8,512,512,2] f32
// out[b,y,x,c] = bilinear sample at (y - flow[...,0], x - flow[...,1]), edge clamp.
//
// R2: 4 threads/pixel channel-parallel. R7/R9: 2 x-adjacent px/thread, 32 regs,
//     32-bit idx, saturatef. R8/R10/R11 block sweep: 64/128 best (53.7us).
// R12: 2D warp tiling — each warp covers an 8-wide x 2-row pixel tile instead
//      of 16 pixels of one row. Query-cell rows of the two tile rows overlap,
//      and x-extent halves: distinct 128B lines per warp drop ~30%, cutting
//      the L1tex tag/wavefront work that has been the invariant floor.
//      Everything else identical to R11.

#define B 8
#define H 512
#define W 512
#define HW (H * W)
#define NPIX (B * HW)
#define NTHREADS_TOTAL (NPIX * 2)   // 4 threads per 2-pixel pair

__device__ __forceinline__ float4 blend4(float4 tl, float4 tr, float4 bl, float4 br,
                                         float ax, float ay)
{
    float4 r;
    float tp, bt;
    tp = tl.x + ax * (tr.x - tl.x); bt = bl.x + ax * (br.x - bl.x); r.x = tp + ay * (bt - tp);
    tp = tl.y + ax * (tr.y - tl.y); bt = bl.y + ax * (br.y - bl.y); r.y = tp + ay * (bt - tp);
    tp = tl.z + ax * (tr.z - tl.z); bt = bl.z + ax * (br.z - bl.z); r.z = tp + ay * (bt - tp);
    tp = tl.w + ax * (tr.w - tl.w); bt = bl.w + ax * (br.w - bl.w); r.w = tp + ay * (bt - tp);
    return r;
}

__global__ __launch_bounds__(64, 32) void warp_kernel(
    const float* __restrict__ image,
    const float* __restrict__ flow,
    float* __restrict__ out)
{
    unsigned t = blockIdx.x * blockDim.x + threadIdx.x;
    unsigned lane = t & 31u;
    unsigned wid  = t >> 5;          // global warp id

    // lane -> (g, pair-in-row, row-in-tile): warp = 8px wide x 2 rows
    unsigned g   = lane & 3u;        // channel group 0..3
    unsigned pr  = (lane >> 2) & 3u; // pair within row, 0..3 (4 pairs = 8 px)
    unsigned row = lane >> 4;        // 0..1

    // warp -> (b, tile-y, tile-x): 64 x-tiles, 256 y-tiles per image
    unsigned tx = wid & 63u;
    unsigned ty = (wid >> 6) & 255u;
    unsigned b  = wid >> 14;

    unsigned y = ty * 2u + row;
    unsigned x = tx * 8u + pr * 2u;  // even; x+1 < 512 always

    unsigned pix0 = (b << 18) + (y << 9) + x;   // even pixel of the pair
    unsigned pp = pix0 >> 1;

    // both pixels' flow in one float4; streamed (no reuse)
    float4 f = __ldcs(((const float4*)flow) + pp);

    // pixel 0
    float qy0 = (float)y - f.x;
    float qx0 = (float)x - f.y;
    float fy0 = fminf(fmaxf(floorf(qy0), 0.0f), (float)(H - 2));
    float fx0 = fminf(fmaxf(floorf(qx0), 0.0f), (float)(W - 2));
    float ay0 = __saturatef(qy0 - fy0);   // fy0 pre-clamped -> identical to clip(0,1)
    float ax0 = __saturatef(qx0 - fx0);
    int iy0 = (int)fy0, ix0 = (int)fx0;

    // pixel 1
    float qy1 = (float)y - f.z;
    float qx1 = (float)(x + 1) - f.w;
    float fy1 = fminf(fmaxf(floorf(qy1), 0.0f), (float)(H - 2));
    float fx1 = fminf(fmaxf(floorf(qx1), 0.0f), (float)(W - 2));
    float ay1 = __saturatef(qy1 - fy1);
    float ax1 = __saturatef(qx1 - fx1);
    int iy1 = (int)fy1, ix1 = (int)fx1;

    // 32-bit float4 indexing throughout (image = 33.5M float4 < 2^31)
    const float4* base = (const float4*)image + b * (unsigned)(HW * 4);
    unsigned a_tl = (unsigned)(iy0 * W + ix0) * 4u + g;
    unsigned a_bl = a_tl + W * 4u;
    unsigned b_tl = (unsigned)(iy1 * W + ix1) * 4u + g;
    unsigned b_bl = b_tl + W * 4u;

    // front-batch all 8 gathers (plus flow already in flight: 9 loads)
    float4 tl0 = __ldg(base + a_tl);
    float4 tr0 = __ldg(base + a_tl + 4);
    float4 bl0 = __ldg(base + a_bl);
    float4 br0 = __ldg(base + a_bl + 4);
    float4 tl1 = __ldg(base + b_tl);
    float4 tr1 = __ldg(base + b_tl + 4);
    float4 bl1 = __ldg(base + b_bl);
    float4 br1 = __ldg(base + b_bl + 4);

    float4 r0 = blend4(tl0, tr0, bl0, br0, ax0, ay0);
    float4 r1 = blend4(tl1, tr1, bl1, br1, ax1, ay1);

    unsigned o0 = pix0 * 4u + g;          // out float4 index, 32-bit
    __stcs(((float4*)out) + o0, r0);
    __stcs(((float4*)out) + o0 + 4u, r1);
}

extern "C" void kernel_launch(void* const* d_in, const int* in_sizes, int n_in,
                              void* d_out, int out_size)
{
    const float* image = (const float*)d_in[0];
    const float* flow  = (const float*)d_in[1];
    float* out = (float*)d_out;

    int threads = 64;
    int blocks = NTHREADS_TOTAL / threads;   // 65536
    warp_kernel<<<blocks, threads>>>(image, flow, out);
}